// round 7
// baseline (speedup 1.0000x reference)
#include <cuda_runtime.h>
#include <cuda_bf16.h>
#include <cstdint>
#include <cstddef>

#define NN 50000
#define EE 800000
#define DF 128            // feature dim for x / hidden
#define KW 256            // weight row length (2*128)

// ---------------- device scratch (static, no allocation) ----------------
__device__ int   g_cnt[NN];            // histogram, then fill-cursor
__device__ int   g_offs[NN + 1];       // CSR row offsets
__device__ int2  g_cw[EE];             // CSR (col, weight-bits) interleaved
__device__ float g_yz[(size_t)NN * 256];  // GEMM output [y|z]
__device__ float g_h [(size_t)NN * DF];   // hidden activations

// ---------------- CSR build ----------------
__global__ void hist_kernel(const int* __restrict__ row) {
    int e = blockIdx.x * blockDim.x + threadIdx.x;
    if (e < EE) atomicAdd(&g_cnt[row[e]], 1);
}

// single-block scan of 50000 counts -> offsets; also primes cursor (= offsets)
__global__ void scan_kernel() {
    __shared__ int s[1024];
    const int tid = threadIdx.x;
    const int CH = (NN + 1023) / 1024;     // 49
    const int base = tid * CH;
    int sum = 0;
    for (int i = 0; i < CH; i++) {
        int idx = base + i;
        if (idx < NN) sum += g_cnt[idx];
    }
    s[tid] = sum;
    __syncthreads();
    for (int off = 1; off < 1024; off <<= 1) {
        int v = (tid >= off) ? s[tid - off] : 0;
        __syncthreads();
        s[tid] += v;
        __syncthreads();
    }
    int run = (tid == 0) ? 0 : s[tid - 1];
    for (int i = 0; i < CH; i++) {
        int idx = base + i;
        if (idx < NN) {
            g_offs[idx] = run;
            int c = g_cnt[idx];
            g_cnt[idx] = run;              // cursor for fill
            run += c;
        }
    }
    if (tid == 1023) g_offs[NN] = s[1023]; // == EE
}

__global__ void fill_kernel(const int* __restrict__ row, const int* __restrict__ col,
                            const float* __restrict__ ew) {
    int e = blockIdx.x * blockDim.x + threadIdx.x;
    if (e < EE) {
        int r = row[e];
        int p = atomicAdd(&g_cnt[r], 1);
        g_cw[p] = make_int2(col[e], __float_as_int(ew[e]));
    }
}

// ---------------- tf32 helpers ----------------
__device__ __forceinline__ float tf32_rna(float x) {
    uint32_t r;
    asm("cvt.rna.tf32.f32 %0, %1;" : "=r"(r) : "f"(x));
    return __uint_as_float(r);
}

__device__ __forceinline__ void mma_tf32(float* d, const uint32_t* a, uint32_t b0, uint32_t b1) {
    asm volatile(
        "mma.sync.aligned.m16n8k8.row.col.f32.tf32.tf32.f32 "
        "{%0,%1,%2,%3}, {%4,%5,%6,%7}, {%8,%9}, {%0,%1,%2,%3};\n"
        : "+f"(d[0]), "+f"(d[1]), "+f"(d[2]), "+f"(d[3])
        : "r"(a[0]), "r"(a[1]), "r"(a[2]), "r"(a[3]), "r"(b0), "r"(b1));
}

// ---------------- projection GEMM (tf32) ----------------
// Computes yz[n, 0:DOUT]   = A @ W[:, 0:128].T   + bias   (the "self" part y)
//          yz[n, DOUT:2*DOUT] = A @ W[:, 128:256].T        (the "agg" part z)
// A: [NN, 128].  W: [DOUT, 256] row-major.  Output row stride 2*DOUT.
// Block tile 128x128, K=128 (BK=32). 8 warps 4(M)x2(N), warp tile 32x64.
template<int DOUT>
__global__ __launch_bounds__(256) void gemm_proj(const float* __restrict__ A,
                                                 const float* __restrict__ W,
                                                 const float* __restrict__ bias,
                                                 float* __restrict__ yz) {
    const int BM = 128, BN = 128, BK = 32;
    const int NOUTROW = 2 * DOUT;             // output row stride
    const int SS = BK + 4;
    __shared__ float As[BM][SS];
    __shared__ float Bs[BN][SS];

    const int tid  = threadIdx.x;
    const int lane = tid & 31;
    const int w    = tid >> 5;
    const int g    = lane >> 2;
    const int t4   = lane & 3;
    const int wm   = (w & 3) * 32;
    const int wn   = (w >> 2) * 64;
    const int m0   = blockIdx.x * BM;
    const int n0   = blockIdx.y * BN;

    float acc[2][8][4];
    #pragma unroll
    for (int i = 0; i < 2; i++)
        #pragma unroll
        for (int j = 0; j < 8; j++)
            #pragma unroll
            for (int q = 0; q < 4; q++) acc[i][j][q] = 0.f;

    for (int kt = 0; kt < DF; kt += BK) {
        // A tile: 128 rows x 32 k = 1024 float4, 4 per thread
        #pragma unroll
        for (int it = 0; it < 4; it++) {
            int idx = tid + it * 256;
            int m = idx >> 3, q = idx & 7;
            int gm = m0 + m;
            float4 v = make_float4(0.f, 0.f, 0.f, 0.f);
            if (gm < NN)
                v = __ldg(((const float4*)(A + (size_t)gm * DF + kt)) + q);
            As[m][q * 4 + 0] = tf32_rna(v.x);
            As[m][q * 4 + 1] = tf32_rna(v.y);
            As[m][q * 4 + 2] = tf32_rna(v.z);
            As[m][q * 4 + 3] = tf32_rna(v.w);
        }
        // B tile: out col n -> W row (n % DOUT), input-col half (n / DOUT)
        #pragma unroll
        for (int it = 0; it < 4; it++) {
            int idx = tid + it * 256;
            int j = idx >> 3, q = idx & 7;
            int n = n0 + j;
            const float* wp = W + (size_t)(n % DOUT) * KW + (n / DOUT) * DF + kt;
            float4 v = __ldg(((const float4*)wp) + q);
            Bs[j][q * 4 + 0] = tf32_rna(v.x);
            Bs[j][q * 4 + 1] = tf32_rna(v.y);
            Bs[j][q * 4 + 2] = tf32_rna(v.z);
            Bs[j][q * 4 + 3] = tf32_rna(v.w);
        }
        __syncthreads();

        #pragma unroll
        for (int ks = 0; ks < 4; ks++) {
            const int k0 = ks * 8;
            uint32_t af[2][4];
            #pragma unroll
            for (int ma = 0; ma < 2; ma++) {
                int r = wm + ma * 16 + g;
                af[ma][0] = __float_as_uint(As[r    ][k0 + t4    ]);
                af[ma][1] = __float_as_uint(As[r + 8][k0 + t4    ]);
                af[ma][2] = __float_as_uint(As[r    ][k0 + t4 + 4]);
                af[ma][3] = __float_as_uint(As[r + 8][k0 + t4 + 4]);
            }
            #pragma unroll
            for (int na = 0; na < 8; na++) {
                int c = wn + na * 8 + g;
                uint32_t b0 = __float_as_uint(Bs[c][k0 + t4    ]);
                uint32_t b1 = __float_as_uint(Bs[c][k0 + t4 + 4]);
                #pragma unroll
                for (int ma = 0; ma < 2; ma++)
                    mma_tf32(acc[ma][na], af[ma], b0, b1);
            }
        }
        __syncthreads();
    }

    // epilogue: bias only on the y half (n < DOUT)
    #pragma unroll
    for (int na = 0; na < 8; na++) {
        int n = n0 + wn + na * 8 + 2 * t4;
        float2 bb = (n < DOUT) ? *(const float2*)&bias[n] : make_float2(0.f, 0.f);
        #pragma unroll
        for (int ma = 0; ma < 2; ma++) {
            int r0 = m0 + wm + ma * 16 + g;
            float2 v0 = make_float2(acc[ma][na][0] + bb.x, acc[ma][na][1] + bb.y);
            float2 v1 = make_float2(acc[ma][na][2] + bb.x, acc[ma][na][3] + bb.y);
            if (r0 < NN)     *(float2*)&yz[(size_t)r0 * NOUTROW + n]       = v0;
            if (r0 + 8 < NN) *(float2*)&yz[(size_t)(r0 + 8) * NOUTROW + n] = v1;
        }
    }
}

// ---------------- fused aggregate + add + (relu) ----------------
// out[n] = act( y[n] + (sum_e w_e * z[col_e]) / max(sum w_e, 1) )
// yz rows: [y (D) | z (D)], stride 2D. One warp per node.
template<int D, int RELU>
__global__ __launch_bounds__(256) void agg_fuse(const float* __restrict__ yz,
                                                float* __restrict__ out) {
    int gw   = (blockIdx.x * blockDim.x + threadIdx.x) >> 5;
    int lane = threadIdx.x & 31;
    if (gw >= NN) return;
    int s = g_offs[gw], e = g_offs[gw + 1];
    float deg = 0.f;

    if (D == 128) {
        float4 acc = make_float4(0.f, 0.f, 0.f, 0.f);
        #pragma unroll 2
        for (int i = s; i < e; i++) {
            int2 cw = __ldg(&g_cw[i]);
            float w = __int_as_float(cw.y);
            float4 v = __ldg(((const float4*)(yz + (size_t)cw.x * (2 * D) + D)) + lane);
            acc.x = fmaf(w, v.x, acc.x);
            acc.y = fmaf(w, v.y, acc.y);
            acc.z = fmaf(w, v.z, acc.z);
            acc.w = fmaf(w, v.w, acc.w);
            deg += w;
        }
        float inv = 1.f / fmaxf(deg, 1.f);
        float4 y = __ldg(((const float4*)(yz + (size_t)gw * (2 * D))) + lane);
        float4 r;
        r.x = fmaf(acc.x, inv, y.x);
        r.y = fmaf(acc.y, inv, y.y);
        r.z = fmaf(acc.z, inv, y.z);
        r.w = fmaf(acc.w, inv, y.w);
        if (RELU) {
            r.x = fmaxf(r.x, 0.f); r.y = fmaxf(r.y, 0.f);
            r.z = fmaxf(r.z, 0.f); r.w = fmaxf(r.w, 0.f);
        }
        ((float4*)(out + (size_t)gw * D))[lane] = r;
    } else {  // D == 64
        float2 acc = make_float2(0.f, 0.f);
        #pragma unroll 2
        for (int i = s; i < e; i++) {
            int2 cw = __ldg(&g_cw[i]);
            float w = __int_as_float(cw.y);
            float2 v = __ldg(((const float2*)(yz + (size_t)cw.x * (2 * D) + D)) + lane);
            acc.x = fmaf(w, v.x, acc.x);
            acc.y = fmaf(w, v.y, acc.y);
            deg += w;
        }
        float inv = 1.f / fmaxf(deg, 1.f);
        float2 y = __ldg(((const float2*)(yz + (size_t)gw * (2 * D))) + lane);
        float2 r;
        r.x = fmaf(acc.x, inv, y.x);
        r.y = fmaf(acc.y, inv, y.y);
        if (RELU) { r.x = fmaxf(r.x, 0.f); r.y = fmaxf(r.y, 0.f); }
        ((float2*)(out + (size_t)gw * D))[lane] = r;
    }
}

// ---------------- launch ----------------
extern "C" void kernel_launch(void* const* d_in, const int* in_sizes, int n_in,
                              void* d_out, int out_size) {
    const float* x  = (const float*)d_in[0];
    const int*   ei = (const int*)  d_in[1];
    const float* ew = (const float*)d_in[2];
    const float* W0 = (const float*)d_in[3];
    const float* b0 = (const float*)d_in[4];
    const float* W1 = (const float*)d_in[5];
    const float* b1 = (const float*)d_in[6];
    const float* W2 = (const float*)d_in[7];
    const float* b2 = (const float*)d_in[8];
    float* out = (float*)d_out;

    const int* row = ei;        // edge_index[0] = dst
    const int* col = ei + EE;   // edge_index[1] = src

    static float* yzp = nullptr;
    static float* hp  = nullptr;
    static int*   cntp = nullptr;
    static cudaStream_t side = nullptr;
    static cudaEvent_t evFork = nullptr, evJoin = nullptr;
    if (!side) {   // first (correctness, non-capture) call: create resources
        cudaGetSymbolAddress((void**)&yzp, g_yz);
        cudaGetSymbolAddress((void**)&hp,  g_h);
        cudaGetSymbolAddress((void**)&cntp, g_cnt);
        cudaStreamCreateWithFlags(&side, cudaStreamNonBlocking);
        cudaEventCreateWithFlags(&evFork, cudaEventDisableTiming);
        cudaEventCreateWithFlags(&evJoin, cudaEventDisableTiming);
    }

    const int aggBlocks = (NN * 32 + 255) / 256;   // one warp per node
    const int gbx = (NN + 127) / 128;              // 391

    // ---- fork: CSR build on side stream, GEMM0 on main stream ----
    cudaEventRecord(evFork, 0);
    cudaStreamWaitEvent(side, evFork, 0);
    cudaMemsetAsync(cntp, 0, NN * sizeof(int), side);
    hist_kernel<<<(EE + 255) / 256, 256, 0, side>>>(row);
    scan_kernel<<<1, 1024, 0, side>>>();
    fill_kernel<<<(EE + 255) / 256, 256, 0, side>>>(row, col, ew);
    cudaEventRecord(evJoin, side);

    // layer 0 GEMM (needs no CSR): x -> [y0|z0]
    gemm_proj<128><<<dim3(gbx, 2), 256>>>(x, W0, b0, yzp);
    cudaStreamWaitEvent(0, evJoin, 0);   // join: agg needs CSR

    // layer 0 agg: h1 = relu(y0 + agg(z0)/deg)
    agg_fuse<128, 1><<<aggBlocks, 256>>>(yzp, hp);

    // layer 1
    gemm_proj<128><<<dim3(gbx, 2), 256>>>(hp, W1, b1, yzp);
    agg_fuse<128, 1><<<aggBlocks, 256>>>(yzp, hp);

    // layer 2 (DOUT=64, no relu) -> d_out
    gemm_proj<64><<<dim3(gbx, 1), 256>>>(hp, W2, b2, yzp);
    agg_fuse<64, 0><<<aggBlocks, 256>>>(yzp, out);
}

// round 11
// speedup vs baseline: 1.0585x; 1.0585x over previous
#include <cuda_runtime.h>
#include <cuda_bf16.h>
#include <cuda_fp16.h>
#include <cstdint>
#include <cstddef>

#define NN 50000
#define EE 800000
#define DF 128            // feature dim for x / hidden
#define KW 256            // weight row length (2*128)

// ---------------- device scratch (static, no allocation) ----------------
__device__ int    g_cnt[NN];            // histogram, then fill-cursor
__device__ int    g_offs[NN + 1];       // CSR row offsets
__device__ int2   g_cw[EE];             // CSR (col, weight-bits) interleaved
__device__ float  g_y[(size_t)NN * DF]; // GEMM "self" output (fp32)
__device__ __half g_z[(size_t)NN * DF]; // GEMM "agg" output (fp16, gathered)
__device__ float  g_h[(size_t)NN * DF]; // hidden activations

// ---------------- CSR build ----------------
__global__ void hist_kernel(const int* __restrict__ row) {
    int e = blockIdx.x * blockDim.x + threadIdx.x;
    if (e < EE) atomicAdd(&g_cnt[row[e]], 1);
}

__global__ void scan_kernel() {
    __shared__ int s[1024];
    const int tid = threadIdx.x;
    const int CH = (NN + 1023) / 1024;     // 49
    const int base = tid * CH;
    int sum = 0;
    for (int i = 0; i < CH; i++) {
        int idx = base + i;
        if (idx < NN) sum += g_cnt[idx];
    }
    s[tid] = sum;
    __syncthreads();
    for (int off = 1; off < 1024; off <<= 1) {
        int v = (tid >= off) ? s[tid - off] : 0;
        __syncthreads();
        s[tid] += v;
        __syncthreads();
    }
    int run = (tid == 0) ? 0 : s[tid - 1];
    for (int i = 0; i < CH; i++) {
        int idx = base + i;
        if (idx < NN) {
            g_offs[idx] = run;
            int c = g_cnt[idx];
            g_cnt[idx] = run;              // cursor for fill
            run += c;
        }
    }
    if (tid == 1023) g_offs[NN] = s[1023]; // == EE
}

__global__ void fill_kernel(const int* __restrict__ row, const int* __restrict__ col,
                            const float* __restrict__ ew) {
    int e = blockIdx.x * blockDim.x + threadIdx.x;
    if (e < EE) {
        int r = row[e];
        int p = atomicAdd(&g_cnt[r], 1);
        g_cw[p] = make_int2(col[e], __float_as_int(ew[e]));
    }
}

// ---------------- tf32 helpers ----------------
__device__ __forceinline__ float tf32_rna(float x) {
    uint32_t r;
    asm("cvt.rna.tf32.f32 %0, %1;" : "=r"(r) : "f"(x));
    return __uint_as_float(r);
}

__device__ __forceinline__ void mma_tf32(float* d,
                                         uint32_t a0, uint32_t a1, uint32_t a2, uint32_t a3,
                                         uint32_t b0, uint32_t b1) {
    asm volatile(
        "mma.sync.aligned.m16n8k8.row.col.f32.tf32.tf32.f32 "
        "{%0,%1,%2,%3}, {%4,%5,%6,%7}, {%8,%9}, {%0,%1,%2,%3};\n"
        : "+f"(d[0]), "+f"(d[1]), "+f"(d[2]), "+f"(d[3])
        : "r"(a0), "r"(a1), "r"(a2), "r"(a3), "r"(b0), "r"(b1));
}

// ---------------- projection GEMM (tf32, single A pass) ----------------
// Y[m, 0:DOUT] = A @ W[:,0:128].T + bias    (fp32)
// Z[m, 0:DOUT] = A @ W[:,128:256].T         (fp16)
// A: [NN,128]. W: [DOUT,256] row-major. BM=64, BN=2*DOUT, BK=32.
// Smem uses k-permuted layout: element k at word (k&3)*8 + (k>>2)  (within 32-k tile)
// so each MMA fragment pair-of-ksteps is one LDS.128.
template<int DOUT>
__global__ __launch_bounds__(256, 2) void gemm2(const float* __restrict__ A,
                                                const float* __restrict__ W,
                                                const float* __restrict__ bias,
                                                float* __restrict__ Y,
                                                __half* __restrict__ Z) {
    const int BM = 64, BN = 2 * DOUT, BK = 32;
    const int NATN = BN / 32;                 // n-atoms per warp (8 or 4)
    const int SS = 36;                        // stride keeps 16B alignment, conflict-free frags
    __shared__ float As[BM][SS];
    __shared__ float Bs[BN][SS];

    const int tid  = threadIdx.x;
    const int lane = tid & 31;
    const int w    = tid >> 5;
    const int g    = lane >> 2;
    const int t4   = lane & 3;
    const int wm   = (w & 1) * 32;            // 2 warp-rows of 32
    const int wn   = (w >> 1) * (BN / 4);     // 4 warp-cols
    const int m0   = blockIdx.x * BM;

    float acc[2][NATN][4];
    #pragma unroll
    for (int i = 0; i < 2; i++)
        #pragma unroll
        for (int j = 0; j < NATN; j++)
            #pragma unroll
            for (int q = 0; q < 4; q++) acc[i][j][q] = 0.f;

    for (int kt = 0; kt < DF; kt += BK) {
        // A tile: 64 rows x 32 k = 512 float4, 2/thread; permuted store
        #pragma unroll
        for (int it = 0; it < 2; it++) {
            int idx = tid + it * 256;
            int m = idx >> 3, q = idx & 7;
            int gm = m0 + m;
            float4 v = make_float4(0.f, 0.f, 0.f, 0.f);
            if (gm < NN)
                v = __ldg(((const float4*)(A + (size_t)gm * DF + kt)) + q);
            As[m][q     ] = tf32_rna(v.x);
            As[m][q +  8] = tf32_rna(v.y);
            As[m][q + 16] = tf32_rna(v.z);
            As[m][q + 24] = tf32_rna(v.w);
        }
        // B tile: BN rows x 32 k; out col j -> W row (j%DOUT), half (j/DOUT)
        #pragma unroll
        for (int it = 0; it < NATN; it++) {
            int idx = tid + it * 256;
            int j = idx >> 3, q = idx & 7;
            int wrow = j & (DOUT - 1);
            int half = (j >= DOUT) ? 1 : 0;
            float4 v = __ldg(((const float4*)(W + (size_t)wrow * KW + half * DF + kt)) + q);
            Bs[j][q     ] = tf32_rna(v.x);
            Bs[j][q +  8] = tf32_rna(v.y);
            Bs[j][q + 16] = tf32_rna(v.z);
            Bs[j][q + 24] = tf32_rna(v.w);
        }
        __syncthreads();

        #pragma unroll
        for (int ksp = 0; ksp < 2; ksp++) {   // each ksp covers 2 k-steps (16 k)
            const int pc = t4 * 8 + ksp * 4;
            float4 a0l = *(const float4*)&As[wm + g     ][pc];
            float4 a0h = *(const float4*)&As[wm + g +  8][pc];
            float4 a1l = *(const float4*)&As[wm + g + 16][pc];
            float4 a1h = *(const float4*)&As[wm + g + 24][pc];
            #pragma unroll
            for (int na = 0; na < NATN; na++) {
                float4 bv = *(const float4*)&Bs[wn + na * 8 + g][pc];
                // k-step even: A cols (k0+t4, k0+t4+4) = (.x, .y); B = (.x, .y)
                mma_tf32(acc[0][na], __float_as_uint(a0l.x), __float_as_uint(a0h.x),
                                      __float_as_uint(a0l.y), __float_as_uint(a0h.y),
                                      __float_as_uint(bv.x),  __float_as_uint(bv.y));
                mma_tf32(acc[1][na], __float_as_uint(a1l.x), __float_as_uint(a1h.x),
                                      __float_as_uint(a1l.y), __float_as_uint(a1h.y),
                                      __float_as_uint(bv.x),  __float_as_uint(bv.y));
                // k-step odd: (.z, .w)
                mma_tf32(acc[0][na], __float_as_uint(a0l.z), __float_as_uint(a0h.z),
                                      __float_as_uint(a0l.w), __float_as_uint(a0h.w),
                                      __float_as_uint(bv.z),  __float_as_uint(bv.w));
                mma_tf32(acc[1][na], __float_as_uint(a1l.z), __float_as_uint(a1h.z),
                                      __float_as_uint(a1l.w), __float_as_uint(a1h.w),
                                      __float_as_uint(bv.z),  __float_as_uint(bv.w));
            }
        }
        __syncthreads();
    }

    // epilogue: cols < DOUT -> Y (+bias, fp32); cols >= DOUT -> Z (fp16)
    #pragma unroll
    for (int na = 0; na < NATN; na++) {
        int col = wn + na * 8 + 2 * t4;
        if (col < DOUT) {
            float2 bb = *(const float2*)&bias[col];
            #pragma unroll
            for (int ma = 0; ma < 2; ma++) {
                int r0 = m0 + wm + ma * 16 + g;
                float2 v0 = make_float2(acc[ma][na][0] + bb.x, acc[ma][na][1] + bb.y);
                float2 v1 = make_float2(acc[ma][na][2] + bb.x, acc[ma][na][3] + bb.y);
                if (r0 < NN)     *(float2*)&Y[(size_t)r0 * DOUT + col]       = v0;
                if (r0 + 8 < NN) *(float2*)&Y[(size_t)(r0 + 8) * DOUT + col] = v1;
            }
        } else {
            int zc = col - DOUT;
            #pragma unroll
            for (int ma = 0; ma < 2; ma++) {
                int r0 = m0 + wm + ma * 16 + g;
                __half2 v0 = __floats2half2_rn(acc[ma][na][0], acc[ma][na][1]);
                __half2 v1 = __floats2half2_rn(acc[ma][na][2], acc[ma][na][3]);
                if (r0 < NN)     *(__half2*)&Z[(size_t)r0 * DOUT + zc]       = v0;
                if (r0 + 8 < NN) *(__half2*)&Z[(size_t)(r0 + 8) * DOUT + zc] = v1;
            }
        }
    }
}

// ---------------- fused aggregate + add + (relu) ----------------
// out[n] = act( Y[n] + (sum_e w_e * Z[col_e]) / max(sum w_e, 1) )
// Z is fp16 (half the gather traffic). One warp per node.
template<int D, int RELU>
__global__ __launch_bounds__(256) void agg_fuse(const float* __restrict__ Y,
                                                const __half* __restrict__ Z,
                                                float* __restrict__ out) {
    int gw   = (blockIdx.x * blockDim.x + threadIdx.x) >> 5;
    int lane = threadIdx.x & 31;
    if (gw >= NN) return;
    int s = g_offs[gw], e = g_offs[gw + 1];
    float deg = 0.f;

    if (D == 128) {
        float4 acc = make_float4(0.f, 0.f, 0.f, 0.f);
        #pragma unroll 2
        for (int i = s; i < e; i++) {
            int2 cw = __ldg(&g_cw[i]);
            float wt = __int_as_float(cw.y);
            uint2 pz = __ldg(((const uint2*)(Z + (size_t)cw.x * D)) + lane);  // 4 halves
            float2 f0 = __half22float2(*(__half2*)&pz.x);
            float2 f1 = __half22float2(*(__half2*)&pz.y);
            acc.x = fmaf(wt, f0.x, acc.x);
            acc.y = fmaf(wt, f0.y, acc.y);
            acc.z = fmaf(wt, f1.x, acc.z);
            acc.w = fmaf(wt, f1.y, acc.w);
            deg += wt;
        }
        float inv = 1.f / fmaxf(deg, 1.f);
        float4 y = __ldg(((const float4*)(Y + (size_t)gw * D)) + lane);
        float4 r;
        r.x = fmaf(acc.x, inv, y.x);
        r.y = fmaf(acc.y, inv, y.y);
        r.z = fmaf(acc.z, inv, y.z);
        r.w = fmaf(acc.w, inv, y.w);
        if (RELU) {
            r.x = fmaxf(r.x, 0.f); r.y = fmaxf(r.y, 0.f);
            r.z = fmaxf(r.z, 0.f); r.w = fmaxf(r.w, 0.f);
        }
        ((float4*)(out + (size_t)gw * D))[lane] = r;
    } else {  // D == 64
        float2 acc = make_float2(0.f, 0.f);
        #pragma unroll 2
        for (int i = s; i < e; i++) {
            int2 cw = __ldg(&g_cw[i]);
            float wt = __int_as_float(cw.y);
            uint32_t pz = __ldg(((const uint32_t*)(Z + (size_t)cw.x * D)) + lane);  // 2 halves
            float2 f0 = __half22float2(*(__half2*)&pz);
            acc.x = fmaf(wt, f0.x, acc.x);
            acc.y = fmaf(wt, f0.y, acc.y);
            deg += wt;
        }
        float inv = 1.f / fmaxf(deg, 1.f);
        float2 y = __ldg(((const float2*)(Y + (size_t)gw * D)) + lane);
        float2 r;
        r.x = fmaf(acc.x, inv, y.x);
        r.y = fmaf(acc.y, inv, y.y);
        if (RELU) { r.x = fmaxf(r.x, 0.f); r.y = fmaxf(r.y, 0.f); }
        ((float2*)(out + (size_t)gw * D))[lane] = r;
    }
}

// ---------------- launch ----------------
extern "C" void kernel_launch(void* const* d_in, const int* in_sizes, int n_in,
                              void* d_out, int out_size) {
    const float* x  = (const float*)d_in[0];
    const int*   ei = (const int*)  d_in[1];
    const float* ew = (const float*)d_in[2];
    const float* W0 = (const float*)d_in[3];
    const float* b0 = (const float*)d_in[4];
    const float* W1 = (const float*)d_in[5];
    const float* b1 = (const float*)d_in[6];
    const float* W2 = (const float*)d_in[7];
    const float* b2 = (const float*)d_in[8];
    float* out = (float*)d_out;

    const int* row = ei;        // edge_index[0] = dst
    const int* col = ei + EE;   // edge_index[1] = src

    static float*  yp = nullptr;
    static __half* zp = nullptr;
    static float*  hp = nullptr;
    static int*    cntp = nullptr;
    static cudaStream_t side = nullptr;
    static cudaEvent_t evFork = nullptr, evJoin = nullptr;
    if (!side) {   // first (correctness, non-capture) call
        cudaGetSymbolAddress((void**)&yp,   g_y);
        cudaGetSymbolAddress((void**)&zp,   g_z);
        cudaGetSymbolAddress((void**)&hp,   g_h);
        cudaGetSymbolAddress((void**)&cntp, g_cnt);
        cudaStreamCreateWithFlags(&side, cudaStreamNonBlocking);
        cudaEventCreateWithFlags(&evFork, cudaEventDisableTiming);
        cudaEventCreateWithFlags(&evJoin, cudaEventDisableTiming);
    }

    const int aggBlocks = (NN * 32 + 255) / 256;   // one warp per node
    const int gbx = (NN + 63) / 64;                // 782

    // ---- fork: CSR build on side stream, GEMM0 on main stream ----
    cudaEventRecord(evFork, 0);
    cudaStreamWaitEvent(side, evFork, 0);
    cudaMemsetAsync(cntp, 0, NN * sizeof(int), side);
    hist_kernel<<<(EE + 255) / 256, 256, 0, side>>>(row);
    scan_kernel<<<1, 1024, 0, side>>>();
    fill_kernel<<<(EE + 255) / 256, 256, 0, side>>>(row, col, ew);
    cudaEventRecord(evJoin, side);

    // layer 0: x -> (y0, z0); needs no CSR
    gemm2<128><<<gbx, 256>>>(x, W0, b0, yp, zp);
    cudaStreamWaitEvent(0, evJoin, 0);             // agg needs CSR
    agg_fuse<128, 1><<<aggBlocks, 256>>>(yp, zp, hp);

    // layer 1
    gemm2<128><<<gbx, 256>>>(hp, W1, b1, yp, zp);
    agg_fuse<128, 1><<<aggBlocks, 256>>>(yp, zp, hp);

    // layer 2 (DOUT=64, no relu) -> d_out
    gemm2<64><<<gbx, 256>>>(hp, W2, b2, yp, zp);
    agg_fuse<64, 0><<<aggBlocks, 256>>>(yp, zp, out);
}

// round 14
// speedup vs baseline: 1.1940x; 1.1280x over previous
#include <cuda_runtime.h>
#include <cuda_bf16.h>
#include <cuda_fp16.h>
#include <cstdint>
#include <cstddef>

#define NN 50000
#define EE 800000
#define DF 128            // feature dim for x / hidden
#define KW 256            // weight row length (2*128)

// ---------------- device scratch (static, no allocation) ----------------
__device__ int    g_cnt[NN];            // histogram, then fill-cursor
__device__ int    g_offs[NN + 1];       // CSR row offsets
__device__ int2   g_cw[EE];             // CSR (col, weight-bits) interleaved
__device__ float  g_y[(size_t)NN * DF]; // GEMM "self" output (fp32)
__device__ __half g_z[(size_t)NN * DF]; // GEMM "agg" output (fp16, gathered)
__device__ float  g_h[(size_t)NN * DF]; // hidden activations

// ---------------- CSR build ----------------
__global__ void hist_kernel(const int* __restrict__ row) {
    int e = blockIdx.x * blockDim.x + threadIdx.x;
    if (e < EE) atomicAdd(&g_cnt[row[e]], 1);
}

__global__ void scan_kernel() {
    __shared__ int s[1024];
    const int tid = threadIdx.x;
    const int CH = (NN + 1023) / 1024;     // 49
    const int base = tid * CH;
    int sum = 0;
    for (int i = 0; i < CH; i++) {
        int idx = base + i;
        if (idx < NN) sum += g_cnt[idx];
    }
    s[tid] = sum;
    __syncthreads();
    for (int off = 1; off < 1024; off <<= 1) {
        int v = (tid >= off) ? s[tid - off] : 0;
        __syncthreads();
        s[tid] += v;
        __syncthreads();
    }
    int run = (tid == 0) ? 0 : s[tid - 1];
    for (int i = 0; i < CH; i++) {
        int idx = base + i;
        if (idx < NN) {
            g_offs[idx] = run;
            int c = g_cnt[idx];
            g_cnt[idx] = run;              // cursor for fill
            run += c;
        }
    }
    if (tid == 1023) g_offs[NN] = s[1023]; // == EE
}

__global__ void fill_kernel(const int* __restrict__ row, const int* __restrict__ col,
                            const float* __restrict__ ew) {
    int e = blockIdx.x * blockDim.x + threadIdx.x;
    if (e < EE) {
        int r = row[e];
        int p = atomicAdd(&g_cnt[r], 1);
        g_cw[p] = make_int2(col[e], __float_as_int(ew[e]));
    }
}

// ---------------- fp16 MMA helper ----------------
__device__ __forceinline__ void mma_f16(float* d, const uint32_t* a, uint32_t b0, uint32_t b1) {
    asm volatile(
        "mma.sync.aligned.m16n8k16.row.col.f32.f16.f16.f32 "
        "{%0,%1,%2,%3}, {%4,%5,%6,%7}, {%8,%9}, {%0,%1,%2,%3};\n"
        : "+f"(d[0]), "+f"(d[1]), "+f"(d[2]), "+f"(d[3])
        : "r"(a[0]), "r"(a[1]), "r"(a[2]), "r"(a[3]), "r"(b0), "r"(b1));
}

// ---------------- projection GEMM (fp16 operands, fp32 accum) ----------------
// Y[m, 0:DOUT] = A @ W[:,0:128].T + bias    (fp32)
// Z[m, 0:DOUT] = A @ W[:,128:256].T         (fp16)
// A: [NN,128] fp32. W: [DOUT,256] fp32 row-major. BM=64, BN=2*DOUT, BK=32.
// Smem: plain [row][k] halves, stride 40 (80B) -> all LDS.32 fragment loads
// conflict-free ((g*20 + t4) mod 32 covers all banks).
template<int DOUT>
__global__ __launch_bounds__(256, 2) void gemm2h(const float* __restrict__ A,
                                                 const float* __restrict__ W,
                                                 const float* __restrict__ bias,
                                                 float* __restrict__ Y,
                                                 __half* __restrict__ Z) {
    const int BM = 64, BN = 2 * DOUT, BK = 32;
    const int NATN = BN / 32;                 // n-atoms per warp (8 or 4)
    const int SS = 40;
    __shared__ __half As[BM][SS];
    __shared__ __half Bs[BN][SS];

    const int tid  = threadIdx.x;
    const int lane = tid & 31;
    const int w    = tid >> 5;
    const int g    = lane >> 2;
    const int t4   = lane & 3;
    const int wm   = (w & 1) * 32;            // 2 warp-rows of 32
    const int wn   = (w >> 1) * (BN / 4);     // 4 warp-cols
    const int m0   = blockIdx.x * BM;

    float acc[2][NATN][4];
    #pragma unroll
    for (int i = 0; i < 2; i++)
        #pragma unroll
        for (int j = 0; j < NATN; j++)
            #pragma unroll
            for (int q = 0; q < 4; q++) acc[i][j][q] = 0.f;

    for (int kt = 0; kt < DF; kt += BK) {
        // A tile: 64 rows x 32 k = 512 float4 reads, 2/thread; convert->half
        #pragma unroll
        for (int it = 0; it < 2; it++) {
            int idx = tid + it * 256;
            int m = idx >> 3, q = idx & 7;
            int gm = m0 + m;
            float4 v = make_float4(0.f, 0.f, 0.f, 0.f);
            if (gm < NN)
                v = __ldg(((const float4*)(A + (size_t)gm * DF + kt)) + q);
            __half2 h0 = __floats2half2_rn(v.x, v.y);
            __half2 h1 = __floats2half2_rn(v.z, v.w);
            *(uint2*)&As[m][q * 4] = make_uint2(*(uint32_t*)&h0, *(uint32_t*)&h1);
        }
        // B tile: BN rows x 32 k; out col j -> W row (j%DOUT), half (j/DOUT)
        #pragma unroll
        for (int it = 0; it < NATN; it++) {
            int idx = tid + it * 256;
            int j = idx >> 3, q = idx & 7;
            int wrow = j & (DOUT - 1);
            int half_ = (j >= DOUT) ? 1 : 0;
            float4 v = __ldg(((const float4*)(W + (size_t)wrow * KW + half_ * DF + kt)) + q);
            __half2 h0 = __floats2half2_rn(v.x, v.y);
            __half2 h1 = __floats2half2_rn(v.z, v.w);
            *(uint2*)&Bs[j][q * 4] = make_uint2(*(uint32_t*)&h0, *(uint32_t*)&h1);
        }
        __syncthreads();

        #pragma unroll
        for (int ks = 0; ks < 2; ks++) {      // two k16 steps per 32-k tile
            const int kb = ks * 16 + 2 * t4;
            uint32_t a[2][4];
            #pragma unroll
            for (int ma = 0; ma < 2; ma++) {
                int r = wm + ma * 16 + g;
                a[ma][0] = *(const uint32_t*)&As[r    ][kb    ];
                a[ma][1] = *(const uint32_t*)&As[r + 8][kb    ];
                a[ma][2] = *(const uint32_t*)&As[r    ][kb + 8];
                a[ma][3] = *(const uint32_t*)&As[r + 8][kb + 8];
            }
            #pragma unroll
            for (int na = 0; na < NATN; na++) {
                int c = wn + na * 8 + g;
                uint32_t b0 = *(const uint32_t*)&Bs[c][kb    ];
                uint32_t b1 = *(const uint32_t*)&Bs[c][kb + 8];
                mma_f16(acc[0][na], a[0], b0, b1);
                mma_f16(acc[1][na], a[1], b0, b1);
            }
        }
        __syncthreads();
    }

    // epilogue: cols < DOUT -> Y (+bias, fp32); cols >= DOUT -> Z (fp16)
    #pragma unroll
    for (int na = 0; na < NATN; na++) {
        int col = wn + na * 8 + 2 * t4;
        if (col < DOUT) {
            float2 bb = *(const float2*)&bias[col];
            #pragma unroll
            for (int ma = 0; ma < 2; ma++) {
                int r0 = m0 + wm + ma * 16 + g;
                float2 v0 = make_float2(acc[ma][na][0] + bb.x, acc[ma][na][1] + bb.y);
                float2 v1 = make_float2(acc[ma][na][2] + bb.x, acc[ma][na][3] + bb.y);
                if (r0 < NN)     *(float2*)&Y[(size_t)r0 * DOUT + col]       = v0;
                if (r0 + 8 < NN) *(float2*)&Y[(size_t)(r0 + 8) * DOUT + col] = v1;
            }
        } else {
            int zc = col - DOUT;
            #pragma unroll
            for (int ma = 0; ma < 2; ma++) {
                int r0 = m0 + wm + ma * 16 + g;
                __half2 v0 = __floats2half2_rn(acc[ma][na][0], acc[ma][na][1]);
                __half2 v1 = __floats2half2_rn(acc[ma][na][2], acc[ma][na][3]);
                if (r0 < NN)     *(__half2*)&Z[(size_t)r0 * DOUT + zc]       = v0;
                if (r0 + 8 < NN) *(__half2*)&Z[(size_t)(r0 + 8) * DOUT + zc] = v1;
            }
        }
    }
}

// ---------------- fused aggregate + add + (relu) ----------------
// out[n] = act( Y[n] + (sum_e w_e * Z[col_e]) / max(sum w_e, 1) )
// Z is fp16. One warp per node; 2-edge unroll x2 accumulator chains for MLP.
template<int D, int RELU>
__global__ __launch_bounds__(256) void agg_fuse(const float* __restrict__ Y,
                                                const __half* __restrict__ Z,
                                                float* __restrict__ out) {
    int gw   = (blockIdx.x * blockDim.x + threadIdx.x) >> 5;
    int lane = threadIdx.x & 31;
    if (gw >= NN) return;
    int s = g_offs[gw], e = g_offs[gw + 1];
    float deg = 0.f;

    if (D == 128) {
        const uint2* Zb = (const uint2*)Z;   // 4 halves per lane-slot
        float4 y = __ldg(((const float4*)(Y + (size_t)gw * D)) + lane);
        float4 acc0 = make_float4(0.f, 0.f, 0.f, 0.f);
        float4 acc1 = make_float4(0.f, 0.f, 0.f, 0.f);
        int i = s;
        #pragma unroll 2
        for (; i + 1 < e; i += 2) {
            int2 c0 = __ldg(&g_cw[i]);
            int2 c1 = __ldg(&g_cw[i + 1]);
            uint2 p0 = __ldg(Zb + (size_t)c0.x * (D / 4) + lane);
            uint2 p1 = __ldg(Zb + (size_t)c1.x * (D / 4) + lane);
            float w0 = __int_as_float(c0.y);
            float w1 = __int_as_float(c1.y);
            float2 a0 = __half22float2(*(__half2*)&p0.x);
            float2 a1 = __half22float2(*(__half2*)&p0.y);
            float2 b0 = __half22float2(*(__half2*)&p1.x);
            float2 b1 = __half22float2(*(__half2*)&p1.y);
            acc0.x = fmaf(w0, a0.x, acc0.x);
            acc0.y = fmaf(w0, a0.y, acc0.y);
            acc0.z = fmaf(w0, a1.x, acc0.z);
            acc0.w = fmaf(w0, a1.y, acc0.w);
            acc1.x = fmaf(w1, b0.x, acc1.x);
            acc1.y = fmaf(w1, b0.y, acc1.y);
            acc1.z = fmaf(w1, b1.x, acc1.z);
            acc1.w = fmaf(w1, b1.y, acc1.w);
            deg += w0 + w1;
        }
        if (i < e) {
            int2 c0 = __ldg(&g_cw[i]);
            uint2 p0 = __ldg(Zb + (size_t)c0.x * (D / 4) + lane);
            float w0 = __int_as_float(c0.y);
            float2 a0 = __half22float2(*(__half2*)&p0.x);
            float2 a1 = __half22float2(*(__half2*)&p0.y);
            acc0.x = fmaf(w0, a0.x, acc0.x);
            acc0.y = fmaf(w0, a0.y, acc0.y);
            acc0.z = fmaf(w0, a1.x, acc0.z);
            acc0.w = fmaf(w0, a1.y, acc0.w);
            deg += w0;
        }
        float inv = 1.f / fmaxf(deg, 1.f);
        float4 r;
        r.x = fmaf(acc0.x + acc1.x, inv, y.x);
        r.y = fmaf(acc0.y + acc1.y, inv, y.y);
        r.z = fmaf(acc0.z + acc1.z, inv, y.z);
        r.w = fmaf(acc0.w + acc1.w, inv, y.w);
        if (RELU) {
            r.x = fmaxf(r.x, 0.f); r.y = fmaxf(r.y, 0.f);
            r.z = fmaxf(r.z, 0.f); r.w = fmaxf(r.w, 0.f);
        }
        ((float4*)(out + (size_t)gw * D))[lane] = r;
    } else {  // D == 64
        const uint32_t* Zb = (const uint32_t*)Z;  // 2 halves per lane-slot
        float2 y = __ldg(((const float2*)(Y + (size_t)gw * D)) + lane);
        float2 acc0 = make_float2(0.f, 0.f);
        float2 acc1 = make_float2(0.f, 0.f);
        int i = s;
        #pragma unroll 2
        for (; i + 1 < e; i += 2) {
            int2 c0 = __ldg(&g_cw[i]);
            int2 c1 = __ldg(&g_cw[i + 1]);
            uint32_t p0 = __ldg(Zb + (size_t)c0.x * (D / 2) + lane);
            uint32_t p1 = __ldg(Zb + (size_t)c1.x * (D / 2) + lane);
            float w0 = __int_as_float(c0.y);
            float w1 = __int_as_float(c1.y);
            float2 a0 = __half22float2(*(__half2*)&p0);
            float2 b0 = __half22float2(*(__half2*)&p1);
            acc0.x = fmaf(w0, a0.x, acc0.x);
            acc0.y = fmaf(w0, a0.y, acc0.y);
            acc1.x = fmaf(w1, b0.x, acc1.x);
            acc1.y = fmaf(w1, b0.y, acc1.y);
            deg += w0 + w1;
        }
        if (i < e) {
            int2 c0 = __ldg(&g_cw[i]);
            uint32_t p0 = __ldg(Zb + (size_t)c0.x * (D / 2) + lane);
            float w0 = __int_as_float(c0.y);
            float2 a0 = __half22float2(*(__half2*)&p0);
            acc0.x = fmaf(w0, a0.x, acc0.x);
            acc0.y = fmaf(w0, a0.y, acc0.y);
            deg += w0;
        }
        float inv = 1.f / fmaxf(deg, 1.f);
        float2 r;
        r.x = fmaf(acc0.x + acc1.x, inv, y.x);
        r.y = fmaf(acc0.y + acc1.y, inv, y.y);
        if (RELU) { r.x = fmaxf(r.x, 0.f); r.y = fmaxf(r.y, 0.f); }
        ((float2*)(out + (size_t)gw * D))[lane] = r;
    }
}

// ---------------- launch ----------------
extern "C" void kernel_launch(void* const* d_in, const int* in_sizes, int n_in,
                              void* d_out, int out_size) {
    const float* x  = (const float*)d_in[0];
    const int*   ei = (const int*)  d_in[1];
    const float* ew = (const float*)d_in[2];
    const float* W0 = (const float*)d_in[3];
    const float* b0 = (const float*)d_in[4];
    const float* W1 = (const float*)d_in[5];
    const float* b1 = (const float*)d_in[6];
    const float* W2 = (const float*)d_in[7];
    const float* b2 = (const float*)d_in[8];
    float* out = (float*)d_out;

    const int* row = ei;        // edge_index[0] = dst
    const int* col = ei + EE;   // edge_index[1] = src

    static float*  yp = nullptr;
    static __half* zp = nullptr;
    static float*  hp = nullptr;
    static int*    cntp = nullptr;
    static cudaStream_t side = nullptr;
    static cudaEvent_t evFork = nullptr, evJoin = nullptr;
    if (!side) {   // first (correctness, non-capture) call
        cudaGetSymbolAddress((void**)&yp,   g_y);
        cudaGetSymbolAddress((void**)&zp,   g_z);
        cudaGetSymbolAddress((void**)&hp,   g_h);
        cudaGetSymbolAddress((void**)&cntp, g_cnt);
        cudaStreamCreateWithFlags(&side, cudaStreamNonBlocking);
        cudaEventCreateWithFlags(&evFork, cudaEventDisableTiming);
        cudaEventCreateWithFlags(&evJoin, cudaEventDisableTiming);
    }

    const int aggBlocks = (NN * 32 + 255) / 256;   // one warp per node
    const int gbx = (NN + 63) / 64;                // 782

    // ---- fork: CSR build on side stream, GEMM0 on main stream ----
    cudaEventRecord(evFork, 0);
    cudaStreamWaitEvent(side, evFork, 0);
    cudaMemsetAsync(cntp, 0, NN * sizeof(int), side);
    hist_kernel<<<(EE + 255) / 256, 256, 0, side>>>(row);
    scan_kernel<<<1, 1024, 0, side>>>();
    fill_kernel<<<(EE + 255) / 256, 256, 0, side>>>(row, col, ew);
    cudaEventRecord(evJoin, side);

    // layer 0: x -> (y0, z0); needs no CSR
    gemm2h<128><<<gbx, 256>>>(x, W0, b0, yp, zp);
    cudaStreamWaitEvent(0, evJoin, 0);             // agg needs CSR
    agg_fuse<128, 1><<<aggBlocks, 256>>>(yp, zp, hp);

    // layer 1
    gemm2h<128><<<gbx, 256>>>(hp, W1, b1, yp, zp);
    agg_fuse<128, 1><<<aggBlocks, 256>>>(yp, zp, hp);

    // layer 2 (DOUT=64, no relu) -> d_out
    gemm2h<64><<<gbx, 256>>>(hp, W2, b2, yp, zp);
    agg_fuse<64, 0><<<aggBlocks, 256>>>(yp, zp, out);
}

// round 15
// speedup vs baseline: 1.3283x; 1.1125x over previous
#include <cuda_runtime.h>
#include <cuda_bf16.h>
#include <cuda_fp16.h>
#include <cstdint>
#include <cstddef>

#define NN 50000
#define EE 800000
#define DF 128            // feature dim for x / hidden
#define KW 256            // weight row length (2*128)

// ---------------- device scratch (static, no allocation) ----------------
__device__ int    g_cnt[NN];            // histogram, then fill-cursor
__device__ int    g_offs[NN + 1];       // CSR row offsets
__device__ int2   g_cw[EE];             // CSR (col, weight-bits) interleaved
__device__ float  g_y[(size_t)NN * DF]; // GEMM "self" output (fp32)
__device__ __half g_z[(size_t)NN * DF]; // GEMM "agg" output (fp16, gathered)
__device__ __half g_xh[(size_t)NN * DF];// fp16 input / hidden activations (reused)
__device__ __half g_wh[3 * 128 * KW];   // fp16 weights W0|W1|W2

// ---------------- CSR build ----------------
__global__ void hist_kernel(const int* __restrict__ row) {
    int e = blockIdx.x * blockDim.x + threadIdx.x;
    if (e < EE) atomicAdd(&g_cnt[row[e]], 1);
}

__global__ void scan_kernel() {
    __shared__ int s[1024];
    const int tid = threadIdx.x;
    const int CH = (NN + 1023) / 1024;     // 49
    const int base = tid * CH;
    int sum = 0;
    for (int i = 0; i < CH; i++) {
        int idx = base + i;
        if (idx < NN) sum += g_cnt[idx];
    }
    s[tid] = sum;
    __syncthreads();
    for (int off = 1; off < 1024; off <<= 1) {
        int v = (tid >= off) ? s[tid - off] : 0;
        __syncthreads();
        s[tid] += v;
        __syncthreads();
    }
    int run = (tid == 0) ? 0 : s[tid - 1];
    for (int i = 0; i < CH; i++) {
        int idx = base + i;
        if (idx < NN) {
            g_offs[idx] = run;
            int c = g_cnt[idx];
            g_cnt[idx] = run;              // cursor for fill
            run += c;
        }
    }
    if (tid == 1023) g_offs[NN] = s[1023]; // == EE
}

__global__ void fill_kernel(const int* __restrict__ row, const int* __restrict__ col,
                            const float* __restrict__ ew) {
    int e = blockIdx.x * blockDim.x + threadIdx.x;
    if (e < EE) {
        int r = row[e];
        int p = atomicAdd(&g_cnt[r], 1);
        g_cw[p] = make_int2(col[e], __float_as_int(ew[e]));
    }
}

// ---------------- fp32 -> fp16 conversion (x and W) ----------------
__global__ void f2h4_kernel(const float* __restrict__ src, __half* __restrict__ dst, int n4) {
    int i = blockIdx.x * blockDim.x + threadIdx.x;
    if (i < n4) {
        float4 v = __ldg(((const float4*)src) + i);
        __half2 a = __floats2half2_rn(v.x, v.y);
        __half2 b = __floats2half2_rn(v.z, v.w);
        ((uint2*)dst)[i] = make_uint2(*(uint32_t*)&a, *(uint32_t*)&b);
    }
}

// ---------------- fp16 MMA + cp.async helpers ----------------
__device__ __forceinline__ void mma_f16(float* d, const uint32_t* a, uint32_t b0, uint32_t b1) {
    asm volatile(
        "mma.sync.aligned.m16n8k16.row.col.f32.f16.f16.f32 "
        "{%0,%1,%2,%3}, {%4,%5,%6,%7}, {%8,%9}, {%0,%1,%2,%3};\n"
        : "+f"(d[0]), "+f"(d[1]), "+f"(d[2]), "+f"(d[3])
        : "r"(a[0]), "r"(a[1]), "r"(a[2]), "r"(a[3]), "r"(b0), "r"(b1));
}

__device__ __forceinline__ void cp_async16(uint32_t dst, const void* src, int srcsize) {
    asm volatile("cp.async.cg.shared.global [%0], [%1], 16, %2;\n"
                 :: "r"(dst), "l"(src), "r"(srcsize));
}
__device__ __forceinline__ void cp_commit() {
    asm volatile("cp.async.commit_group;\n");
}
__device__ __forceinline__ void cp_wait1() {
    asm volatile("cp.async.wait_group 1;\n");
}

// ---------------- projection GEMM (fp16 in gmem, cp.async 2-stage) ----------------
// Y[m, 0:DOUT] = A @ W[:,0:128].T + bias    (fp32)
// Z[m, 0:DOUT] = A @ W[:,128:256].T         (fp16)
// A: [NN,128] fp16. Wh: [DOUT,256] fp16 row-major. BM=64, BN=2*DOUT, BK=32.
// Smem rows stride 40 halves (80B, 16B-aligned) -> conflict-free LDS frags.
template<int DOUT>
__global__ __launch_bounds__(256, 2) void gemm_h(const __half* __restrict__ A,
                                                 const __half* __restrict__ Wh,
                                                 const float* __restrict__ bias,
                                                 float* __restrict__ Y,
                                                 __half* __restrict__ Z) {
    const int BM = 64, BN = 2 * DOUT, BK = 32;
    const int NATN = BN / 32;                 // n-atoms per warp (8 or 4)
    const int SS = 40;
    extern __shared__ __half sm[];
    __half* Asb = sm;                         // [2][BM][SS]
    __half* Bsb = sm + 2 * BM * SS;           // [2][BN][SS]
#define AS_(st, m, k) Asb[((st) * BM + (m)) * SS + (k)]
#define BS_(st, j, k) Bsb[((st) * BN + (j)) * SS + (k)]

    const int tid  = threadIdx.x;
    const int lane = tid & 31;
    const int w    = tid >> 5;
    const int g    = lane >> 2;
    const int t4   = lane & 3;
    const int wm   = (w & 1) * 32;            // 2 warp-rows of 32
    const int wn   = (w >> 1) * (BN / 4);     // 4 warp-cols
    const int m0   = blockIdx.x * BM;

    float acc[2][NATN][4];
    #pragma unroll
    for (int i = 0; i < 2; i++)
        #pragma unroll
        for (int j = 0; j < NATN; j++)
            #pragma unroll
            for (int q = 0; q < 4; q++) acc[i][j][q] = 0.f;

    // stage issue: A = BM*4 = 256 chunks (1/thread); B = BN*4 chunks (BN/64 /thread)
    auto issue = [&](int st, int kt) {
        {
            int m = tid >> 2, q = tid & 3;
            int gm = m0 + m;
            const __half* src = (gm < NN) ? (A + (size_t)gm * DF + kt + q * 8) : A;
            int zs = (gm < NN) ? 16 : 0;
            cp_async16((uint32_t)__cvta_generic_to_shared(&AS_(st, m, q * 8)), src, zs);
        }
        #pragma unroll
        for (int it = 0; it < BN / 64; it++) {
            int c = tid + it * 256;
            int j = c >> 2, q = c & 3;
            int wrow = j & (DOUT - 1);
            int half_ = (j >= DOUT) ? 1 : 0;
            const __half* src = Wh + (size_t)wrow * KW + half_ * DF + kt + q * 8;
            cp_async16((uint32_t)__cvta_generic_to_shared(&BS_(st, j, q * 8)), src, 16);
        }
    };

    issue(0, 0);
    cp_commit();

    #pragma unroll
    for (int t = 0; t < DF / BK; t++) {       // 4 k-tiles
        if (t + 1 < DF / BK) issue((t + 1) & 1, (t + 1) * BK);
        cp_commit();
        cp_wait1();                            // stage t landed
        __syncthreads();

        const int st = t & 1;
        #pragma unroll
        for (int ks = 0; ks < 2; ks++) {      // two k16 steps per 32-k tile
            const int kb = ks * 16 + 2 * t4;
            uint32_t a[2][4];
            #pragma unroll
            for (int ma = 0; ma < 2; ma++) {
                int r = wm + ma * 16 + g;
                a[ma][0] = *(const uint32_t*)&AS_(st, r,     kb    );
                a[ma][1] = *(const uint32_t*)&AS_(st, r + 8, kb    );
                a[ma][2] = *(const uint32_t*)&AS_(st, r,     kb + 8);
                a[ma][3] = *(const uint32_t*)&AS_(st, r + 8, kb + 8);
            }
            #pragma unroll
            for (int na = 0; na < NATN; na++) {
                int c = wn + na * 8 + g;
                uint32_t b0 = *(const uint32_t*)&BS_(st, c, kb    );
                uint32_t b1 = *(const uint32_t*)&BS_(st, c, kb + 8);
                mma_f16(acc[0][na], a[0], b0, b1);
                mma_f16(acc[1][na], a[1], b0, b1);
            }
        }
        __syncthreads();                       // protect buffer reuse
    }

    // epilogue: cols < DOUT -> Y (+bias, fp32); cols >= DOUT -> Z (fp16)
    #pragma unroll
    for (int na = 0; na < NATN; na++) {
        int col = wn + na * 8 + 2 * t4;
        if (col < DOUT) {
            float2 bb = *(const float2*)&bias[col];
            #pragma unroll
            for (int ma = 0; ma < 2; ma++) {
                int r0 = m0 + wm + ma * 16 + g;
                float2 v0 = make_float2(acc[ma][na][0] + bb.x, acc[ma][na][1] + bb.y);
                float2 v1 = make_float2(acc[ma][na][2] + bb.x, acc[ma][na][3] + bb.y);
                if (r0 < NN)     *(float2*)&Y[(size_t)r0 * DOUT + col]       = v0;
                if (r0 + 8 < NN) *(float2*)&Y[(size_t)(r0 + 8) * DOUT + col] = v1;
            }
        } else {
            int zc = col - DOUT;
            #pragma unroll
            for (int ma = 0; ma < 2; ma++) {
                int r0 = m0 + wm + ma * 16 + g;
                __half2 v0 = __floats2half2_rn(acc[ma][na][0], acc[ma][na][1]);
                __half2 v1 = __floats2half2_rn(acc[ma][na][2], acc[ma][na][3]);
                if (r0 < NN)     *(__half2*)&Z[(size_t)r0 * DOUT + zc]       = v0;
                if (r0 + 8 < NN) *(__half2*)&Z[(size_t)(r0 + 8) * DOUT + zc] = v1;
            }
        }
    }
#undef AS_
#undef BS_
}

// ---------------- fused aggregate + add + (relu) ----------------
// res[n] = act( Y[n] + (sum_e w_e * Z[col_e]) / max(sum w_e, 1) )
// Half-warp (16 lanes) per node: D=128 -> LDG.128/lane, out fp16.
//                                D=64  -> LDG.64/lane,  out fp32.
template<int D, int RELU>
__global__ __launch_bounds__(256) void agg_fuse(const float* __restrict__ Y,
                                                const __half* __restrict__ Z,
                                                void* __restrict__ outv) {
    int node = (blockIdx.x * blockDim.x + threadIdx.x) >> 4;
    int l    = threadIdx.x & 15;
    if (node >= NN) return;
    int s = g_offs[node], e = g_offs[node + 1];

    if (D == 128) {
        const uint4* Zb = (const uint4*)Z;   // 16 uint4 (8 halves each) per row
        float acc0[8], acc1[8];
        #pragma unroll
        for (int k = 0; k < 8; k++) { acc0[k] = 0.f; acc1[k] = 0.f; }
        float deg0 = 0.f, deg1 = 0.f;
        int i = s;
        #pragma unroll 2
        for (; i + 1 < e; i += 2) {
            int2 c0 = __ldg(&g_cw[i]);
            int2 c1 = __ldg(&g_cw[i + 1]);
            uint4 p0 = __ldg(Zb + (size_t)c0.x * 16 + l);
            uint4 p1 = __ldg(Zb + (size_t)c1.x * 16 + l);
            float w0 = __int_as_float(c0.y), w1 = __int_as_float(c1.y);
            const __half2* h0 = (const __half2*)&p0;
            const __half2* h1 = (const __half2*)&p1;
            #pragma unroll
            for (int j = 0; j < 4; j++) {
                float2 f0 = __half22float2(h0[j]);
                float2 f1 = __half22float2(h1[j]);
                acc0[2 * j]     = fmaf(w0, f0.x, acc0[2 * j]);
                acc0[2 * j + 1] = fmaf(w0, f0.y, acc0[2 * j + 1]);
                acc1[2 * j]     = fmaf(w1, f1.x, acc1[2 * j]);
                acc1[2 * j + 1] = fmaf(w1, f1.y, acc1[2 * j + 1]);
            }
            deg0 += w0; deg1 += w1;
        }
        if (i < e) {
            int2 c0 = __ldg(&g_cw[i]);
            uint4 p0 = __ldg(Zb + (size_t)c0.x * 16 + l);
            float w0 = __int_as_float(c0.y);
            const __half2* h0 = (const __half2*)&p0;
            #pragma unroll
            for (int j = 0; j < 4; j++) {
                float2 f0 = __half22float2(h0[j]);
                acc0[2 * j]     = fmaf(w0, f0.x, acc0[2 * j]);
                acc0[2 * j + 1] = fmaf(w0, f0.y, acc0[2 * j + 1]);
            }
            deg0 += w0;
        }
        float inv = 1.f / fmaxf(deg0 + deg1, 1.f);
        const float4* Yb = (const float4*)(Y + (size_t)node * 128);
        float4 y0 = __ldg(Yb + 2 * l);
        float4 y1 = __ldg(Yb + 2 * l + 1);
        float r[8];
        r[0] = fmaf(acc0[0] + acc1[0], inv, y0.x);
        r[1] = fmaf(acc0[1] + acc1[1], inv, y0.y);
        r[2] = fmaf(acc0[2] + acc1[2], inv, y0.z);
        r[3] = fmaf(acc0[3] + acc1[3], inv, y0.w);
        r[4] = fmaf(acc0[4] + acc1[4], inv, y1.x);
        r[5] = fmaf(acc0[5] + acc1[5], inv, y1.y);
        r[6] = fmaf(acc0[6] + acc1[6], inv, y1.z);
        r[7] = fmaf(acc0[7] + acc1[7], inv, y1.w);
        if (RELU) {
            #pragma unroll
            for (int k = 0; k < 8; k++) r[k] = fmaxf(r[k], 0.f);
        }
        __half2 o0 = __floats2half2_rn(r[0], r[1]);
        __half2 o1 = __floats2half2_rn(r[2], r[3]);
        __half2 o2 = __floats2half2_rn(r[4], r[5]);
        __half2 o3 = __floats2half2_rn(r[6], r[7]);
        uint4 pk = make_uint4(*(uint32_t*)&o0, *(uint32_t*)&o1,
                              *(uint32_t*)&o2, *(uint32_t*)&o3);
        ((uint4*)((__half*)outv + (size_t)node * 128))[l] = pk;
    } else {  // D == 64, fp32 out
        const uint2* Zb = (const uint2*)Z;   // 16 uint2 (4 halves each) per row
        float acc0[4], acc1[4];
        #pragma unroll
        for (int k = 0; k < 4; k++) { acc0[k] = 0.f; acc1[k] = 0.f; }
        float deg0 = 0.f, deg1 = 0.f;
        int i = s;
        #pragma unroll 2
        for (; i + 1 < e; i += 2) {
            int2 c0 = __ldg(&g_cw[i]);
            int2 c1 = __ldg(&g_cw[i + 1]);
            uint2 p0 = __ldg(Zb + (size_t)c0.x * 16 + l);
            uint2 p1 = __ldg(Zb + (size_t)c1.x * 16 + l);
            float w0 = __int_as_float(c0.y), w1 = __int_as_float(c1.y);
            float2 f0a = __half22float2(*(__half2*)&p0.x);
            float2 f0b = __half22float2(*(__half2*)&p0.y);
            float2 f1a = __half22float2(*(__half2*)&p1.x);
            float2 f1b = __half22float2(*(__half2*)&p1.y);
            acc0[0] = fmaf(w0, f0a.x, acc0[0]);
            acc0[1] = fmaf(w0, f0a.y, acc0[1]);
            acc0[2] = fmaf(w0, f0b.x, acc0[2]);
            acc0[3] = fmaf(w0, f0b.y, acc0[3]);
            acc1[0] = fmaf(w1, f1a.x, acc1[0]);
            acc1[1] = fmaf(w1, f1a.y, acc1[1]);
            acc1[2] = fmaf(w1, f1b.x, acc1[2]);
            acc1[3] = fmaf(w1, f1b.y, acc1[3]);
            deg0 += w0; deg1 += w1;
        }
        if (i < e) {
            int2 c0 = __ldg(&g_cw[i]);
            uint2 p0 = __ldg(Zb + (size_t)c0.x * 16 + l);
            float w0 = __int_as_float(c0.y);
            float2 f0a = __half22float2(*(__half2*)&p0.x);
            float2 f0b = __half22float2(*(__half2*)&p0.y);
            acc0[0] = fmaf(w0, f0a.x, acc0[0]);
            acc0[1] = fmaf(w0, f0a.y, acc0[1]);
            acc0[2] = fmaf(w0, f0b.x, acc0[2]);
            acc0[3] = fmaf(w0, f0b.y, acc0[3]);
            deg0 += w0;
        }
        float inv = 1.f / fmaxf(deg0 + deg1, 1.f);
        float4 y = __ldg(((const float4*)(Y + (size_t)node * 64)) + l);
        float4 r;
        r.x = fmaf(acc0[0] + acc1[0], inv, y.x);
        r.y = fmaf(acc0[1] + acc1[1], inv, y.y);
        r.z = fmaf(acc0[2] + acc1[2], inv, y.z);
        r.w = fmaf(acc0[3] + acc1[3], inv, y.w);
        if (RELU) {
            r.x = fmaxf(r.x, 0.f); r.y = fmaxf(r.y, 0.f);
            r.z = fmaxf(r.z, 0.f); r.w = fmaxf(r.w, 0.f);
        }
        ((float4*)((float*)outv + (size_t)node * 64))[l] = r;
    }
}

// ---------------- launch ----------------
extern "C" void kernel_launch(void* const* d_in, const int* in_sizes, int n_in,
                              void* d_out, int out_size) {
    const float* x  = (const float*)d_in[0];
    const int*   ei = (const int*)  d_in[1];
    const float* ew = (const float*)d_in[2];
    const float* W0 = (const float*)d_in[3];
    const float* b0 = (const float*)d_in[4];
    const float* W1 = (const float*)d_in[5];
    const float* b1 = (const float*)d_in[6];
    const float* W2 = (const float*)d_in[7];
    const float* b2 = (const float*)d_in[8];
    float* out = (float*)d_out;

    const int* row = ei;        // edge_index[0] = dst
    const int* col = ei + EE;   // edge_index[1] = src

    static float*  yp = nullptr;
    static __half* zp = nullptr;
    static __half* xhp = nullptr;
    static __half* whp = nullptr;
    static int*    cntp = nullptr;
    static cudaStream_t side = nullptr;
    static cudaEvent_t evFork = nullptr, evJoin = nullptr;
    if (!side) {   // first (correctness, non-capture) call
        cudaGetSymbolAddress((void**)&yp,   g_y);
        cudaGetSymbolAddress((void**)&zp,   g_z);
        cudaGetSymbolAddress((void**)&xhp,  g_xh);
        cudaGetSymbolAddress((void**)&whp,  g_wh);
        cudaGetSymbolAddress((void**)&cntp, g_cnt);
        cudaStreamCreateWithFlags(&side, cudaStreamNonBlocking);
        cudaEventCreateWithFlags(&evFork, cudaEventDisableTiming);
        cudaEventCreateWithFlags(&evJoin, cudaEventDisableTiming);
        cudaFuncSetAttribute(gemm_h<128>, cudaFuncAttributeMaxDynamicSharedMemorySize,
                             2 * (64 + 256) * 40 * (int)sizeof(__half));
        cudaFuncSetAttribute(gemm_h<64>, cudaFuncAttributeMaxDynamicSharedMemorySize,
                             2 * (64 + 128) * 40 * (int)sizeof(__half));
    }

    __half* w0h = whp;
    __half* w1h = whp + 128 * KW;
    __half* w2h = whp + 2 * 128 * KW;

    const int aggBlocks = (NN * 16 + 255) / 256;   // half-warp per node
    const int gbx = (NN + 63) / 64;                // 782
    const int smem128 = 2 * (64 + 256) * 40 * (int)sizeof(__half);
    const int smem64  = 2 * (64 + 128) * 40 * (int)sizeof(__half);

    // ---- fork: CSR build on side stream ----
    cudaEventRecord(evFork, 0);
    cudaStreamWaitEvent(side, evFork, 0);
    cudaMemsetAsync(cntp, 0, NN * sizeof(int), side);
    hist_kernel<<<(EE + 255) / 256, 256, 0, side>>>(row);
    scan_kernel<<<1, 1024, 0, side>>>();
    fill_kernel<<<(EE + 255) / 256, 256, 0, side>>>(row, col, ew);
    cudaEventRecord(evJoin, side);

    // ---- main: fp16 conversions, then layer 0 GEMM (no CSR needed) ----
    f2h4_kernel<<<(NN * DF / 4 + 255) / 256, 256>>>(x, xhp, NN * DF / 4);
    f2h4_kernel<<<(128 * KW / 4 + 255) / 256, 256>>>(W0, w0h, 128 * KW / 4);
    f2h4_kernel<<<(128 * KW / 4 + 255) / 256, 256>>>(W1, w1h, 128 * KW / 4);
    f2h4_kernel<<<(64 * KW / 4 + 255) / 256, 256>>>(W2, w2h, 64 * KW / 4);

    // layer 0: xh -> (y, z)
    gemm_h<128><<<gbx, 256, smem128>>>(xhp, w0h, b0, yp, zp);
    cudaStreamWaitEvent(0, evJoin, 0);             // agg needs CSR
    agg_fuse<128, 1><<<aggBlocks, 256>>>(yp, zp, xhp);   // h1 (fp16) reuses xh

    // layer 1
    gemm_h<128><<<gbx, 256, smem128>>>(xhp, w1h, b1, yp, zp);
    agg_fuse<128, 1><<<aggBlocks, 256>>>(yp, zp, xhp);   // h2 (fp16)

    // layer 2 (DOUT=64, no relu) -> d_out (fp32)
    gemm_h<64><<<gbx, 256, smem64>>>(xhp, w2h, b2, yp, zp);
    agg_fuse<64, 0><<<aggBlocks, 256>>>(yp, zp, out);
}